// round 14
// baseline (speedup 1.0000x reference)
#include <cuda_runtime.h>
#include <math_constants.h>

// Shapes: img (B=2, C=1, D=192, H=192, W=192) float32.
static constexpr int B   = 2;
static constexpr int DD  = 192;
static constexpr int HH  = 192;
static constexpr int WW  = 192;
static constexpr int PLANE = HH * WW;        // 36864
static constexpr int VOL   = DD * PLANE;     // 7077888
static constexpr int NTOT  = B * VOL;        // 14155776
static constexpr int WWW   = WW / 2;         // 96 gmem float2 words/row

static constexpr int NTHR = 512;
static constexpr int ZCHUNK = 48;            // z0 % 6 == 0
static constexpr int NCH    = DD / ZCHUNK;   // 4

// float2-word smem geometry
static constexpr int AWW = 18;               // A: 36 rows x 18 words (halo 2)
static constexpr int APW = 36 * AWW;         // 648
static constexpr int RWW = 16;               // rx: 34 rows x 16 words
static constexpr int RPW = 34 * RWW;         // 544

static constexpr int SM_BYTES = (6 * APW + 6 * RPW) * 8;  // 57216

// Ping-pong erosion buffers (scratch: __device__ globals, no allocation).
__device__ float g_buf0[NTOT];
__device__ float g_buf1[NTOT];

// One fused soft-skeletonize step:
//   Eout = soft_erode(A)                 (7-pt cross min, +inf pad)
//   d    = dilate3x3x3(Eout)             (-inf pad)
//   delta = relu(A - d)
//   skel  = FIRST ? delta : skel + relu(delta - skel*delta)
// float2 datapath; erode->rowmax fused via warp shuffles (no eb plane);
// 2 planes per iteration with ONE __syncthreads per body; A-plane LDGs
// prefetched one body ahead in registers.
template <int FIRST>
__global__ __launch_bounds__(NTHR, 2)
void fused_step(const float* __restrict__ A,
                float* __restrict__ Eout,
                float* __restrict__ skel)
{
    extern __shared__ float2 sm2[];
    float2* As2 = sm2;                        // 6 planes, slot = j%6
    float2* rx2 = sm2 + 6 * APW;              // 6 planes row-max, slot = j%6

    const int tid = threadIdx.x;
    const int x0  = blockIdx.x * 32;
    const int y0  = blockIdx.y * 32;
    const int bz  = blockIdx.z;
    const int bb  = bz >> 2;                  // NCH == 4
    const int z0  = (bz & 3) * ZCHUNK;        // z0 % 6 == 0
    const int z1  = z0 + ZCHUNK;

    const float* __restrict__ Ab = A    + bb * VOL;
    float* __restrict__ EbB      = Eout + bb * VOL;
    float* __restrict__ SbB      = skel + bb * VOL;

    const float NINF = -CUDART_INF_F;
    const float2 PINF2 = make_float2(CUDART_INF_F, CUDART_INF_F);

    // ================= z-invariant per-thread precomputation ==============
    const int r = tid >> 4;                   // 0..31 (rx/out row)
    const int k = tid & 15;                   // x-pair index

    const int  bA   = (r + 1) * AWW + k;      // A word base (e row r)
    const bool valE = ((unsigned)(y0 + r - 1) < (unsigned)HH);
    const bool stM  = (r >= 1);               // e rows 1..32 are stored
    const int  gEM  = (y0 + r - 1) * WWW + (x0 >> 1) + k;

    const bool act2e = tid < 32;              // second e rows 32,33 (warp 0)
    const bool stM2  = tid < 16;              // row 32 stored
    const bool valE2 = (tid < 16) || (y0 < 160);

    const bool edgeL = (x0 != 0);             // e col 0 in-bounds
    const bool edgeR = (x0 != 160);           // e col 33 in-bounds

    const int gw = (y0 + r) * WWW + (x0 >> 1) + k;   // out word

    // loadA: 648 words = 512 + 136
    const bool actL1 = tid < (APW - NTHR);
    int la0g, la1g; bool la0v, la1v;
    {
        int row0 = tid / AWW, c0 = tid - row0 * AWW;
        int gy = y0 + row0 - 2, gx = x0 + 2 * c0 - 2;
        la0v = ((unsigned)gy < (unsigned)HH) && ((unsigned)gx < (unsigned)WW);
        la0g = la0v ? gy * WWW + (gx >> 1) : 0;
        int wi = tid + NTHR;
        int row1 = wi / AWW, c1 = wi - row1 * AWW;
        gy = y0 + row1 - 2; gx = x0 + 2 * c1 - 2;
        la1v = actL1 && ((unsigned)gy < (unsigned)HH) && ((unsigned)gx < (unsigned)WW);
        la1g = la1v ? gy * WWW + (gx >> 1) : 0;
    }

    float2 capA, capB, carry;
    float2 pf0a, pf0b, pf1a, pf1b;            // prefetched A planes (regs)

    // ========================= helpers ====================================

    auto loadAfn = [&](const float* src, bool zv, int slot) {
        float2* s = As2 + slot * APW;
        const float2* g = (const float2*)src;
        float2 v0 = (zv && la0v) ? __ldg(g + la0g) : PINF2;
        s[tid] = v0;
        if (actL1) {
            float2 v1 = (zv && la1v) ? __ldg(g + la1g) : PINF2;
            s[tid + NTHR] = v1;
        }
    };

    auto ldPrefetch = [&](const float* srcA, const float* srcB,
                          bool zvA, bool zvB) {
        const float2* g0 = (const float2*)srcA;
        const float2* g1 = (const float2*)srcB;
        pf0a = (zvA && la0v) ? __ldg(g0 + la0g) : PINF2;
        pf1a = (zvB && la0v) ? __ldg(g1 + la0g) : PINF2;
        if (actL1) {
            pf0b = (zvA && la1v) ? __ldg(g0 + la1g) : PINF2;
            pf1b = (zvB && la1v) ? __ldg(g1 + la1g) : PINF2;
        }
    };

    auto stsPrefetch = [&](int slotA, int slotB) {
        As2[slotA * APW + tid] = pf0a;
        As2[slotB * APW + tid] = pf1a;
        if (actL1) {
            As2[slotA * APW + tid + NTHR] = pf0b;
            As2[slotB * APW + tid + NTHR] = pf1b;
        }
    };

    // Fused erode + x-rowmax for one plane. Writes rx slot (== sC slot) and
    // optionally stores E to gmem. Returns dn word (A-center of out row).
    auto er = [&](int sC, int sM, int sP, bool jv, bool st, float* pE)
        -> float2 {
        const float2* C = As2 + sC * APW;
        const float2* M = As2 + sM * APW;
        const float2* P = As2 + sP * APW;
        float2* R = rx2 + sC * RPW;

        // main pair: e cols 2k+1, 2k+2 at e-row r
        float2 w0 = C[bA], w1 = C[bA + 1], w2 = C[bA + 2];
        float2 up = C[bA + 1 - AWW], dn = C[bA + 1 + AWW];
        float2 zm = M[bA + 1], zp = P[bA + 1];
        float e0 = fminf(fminf(w1.x, fminf(up.x, dn.x)), fminf(zm.x, zp.x));
        e0 = fminf(e0, fminf(w0.y, w1.y));
        float e1 = fminf(fminf(w1.y, fminf(up.y, dn.y)), fminf(zm.y, zp.y));
        e1 = fminf(e1, fminf(w1.x, w2.x));
        {
            bool v = jv && valE;
            e0 = v ? e0 : NINF;
            e1 = v ? e1 : NINF;
            // edge cols 0 (k==0) / 33 (k==15)
            float eEdge = NINF;
            if (k == 0) {
                if (edgeL) {
                    float m = fminf(fminf(w0.x, w0.y), w1.x);
                    m = fminf(m, fminf(C[bA - AWW].y, C[bA + AWW].y));
                    m = fminf(m, fminf(M[bA].y, P[bA].y));
                    eEdge = v ? m : NINF;
                }
            } else if (k == 15) {
                if (edgeR) {
                    float m = fminf(fminf(w1.y, w2.x), w2.y);
                    m = fminf(m, fminf(C[bA + 2 - AWW].x, C[bA + 2 + AWW].x));
                    m = fminf(m, fminf(M[bA + 2].x, P[bA + 2].x));
                    eEdge = v ? m : NINF;
                }
            }
            float eL = __shfl_up_sync(0xffffffffu, e1, 1, 16);
            float eR = __shfl_down_sync(0xffffffffu, e0, 1, 16);
            if (k == 0)  eL = eEdge;
            if (k == 15) eR = eEdge;
            float2 rxv;
            float c01 = fmaxf(e0, e1);
            rxv.x = fmaxf(eL, c01);
            rxv.y = fmaxf(c01, eR);
            R[tid] = rxv;
            if (st && stM) {
                float2 o; o.x = e0; o.y = e1;
                ((float2*)pE)[gEM] = o;
            }
        }
        // second pair: e rows 32,33 (warp 0 only, uniform branch)
        if (act2e) {
            const int bA2 = bA + 32 * AWW;
            float2 W0 = C[bA2], W1 = C[bA2 + 1], W2 = C[bA2 + 2];
            float2 UP = C[bA2 + 1 - AWW], DN = C[bA2 + 1 + AWW];
            float2 ZM = M[bA2 + 1], ZP = P[bA2 + 1];
            float f0 = fminf(fminf(W1.x, fminf(UP.x, DN.x)), fminf(ZM.x, ZP.x));
            f0 = fminf(f0, fminf(W0.y, W1.y));
            float f1 = fminf(fminf(W1.y, fminf(UP.y, DN.y)), fminf(ZM.y, ZP.y));
            f1 = fminf(f1, fminf(W1.x, W2.x));
            bool v2 = jv && valE2;
            f0 = v2 ? f0 : NINF;
            f1 = v2 ? f1 : NINF;
            float fEdge = NINF;
            if (k == 0) {
                if (edgeL) {
                    float m = fminf(fminf(W0.x, W0.y), W1.x);
                    m = fminf(m, fminf(C[bA2 - AWW].y, C[bA2 + AWW].y));
                    m = fminf(m, fminf(M[bA2].y, P[bA2].y));
                    fEdge = v2 ? m : NINF;
                }
            } else if (k == 15) {
                if (edgeR) {
                    float m = fminf(fminf(W1.y, W2.x), W2.y);
                    m = fminf(m, fminf(C[bA2 + 2 - AWW].x, C[bA2 + 2 + AWW].x));
                    m = fminf(m, fminf(M[bA2 + 2].x, P[bA2 + 2].x));
                    fEdge = v2 ? m : NINF;
                }
            }
            float fL = __shfl_up_sync(0xffffffffu, f1, 1, 16);
            float fR = __shfl_down_sync(0xffffffffu, f0, 1, 16);
            if (k == 0)  fL = fEdge;
            if (k == 15) fR = fEdge;
            float2 rxv;
            float c01 = fmaxf(f0, f1);
            rxv.x = fmaxf(fL, c01);
            rxv.y = fmaxf(c01, fR);
            R[NTHR + tid] = rxv;
            if (st && stM2) {
                float2 o; o.x = f0; o.y = f1;
                ((float2*)pE)[gEM + 32 * WWW] = o;
            }
        }
        return dn;
    };

    auto do_output = [&](int s0, int s1, int s2, float* pS, float2 a,
                         float2 sPre) {
        const float2* R0 = rx2 + s0 * RPW;
        const float2* R1 = rx2 + s1 * RPW;
        const float2* R2 = rx2 + s2 * RPW;
        float2 m = R0[tid];
        float2 t;
        t = R0[tid + RWW];     m.x = fmaxf(m.x, t.x); m.y = fmaxf(m.y, t.y);
        t = R0[tid + 2*RWW];   m.x = fmaxf(m.x, t.x); m.y = fmaxf(m.y, t.y);
        t = R1[tid];           m.x = fmaxf(m.x, t.x); m.y = fmaxf(m.y, t.y);
        t = R1[tid + RWW];     m.x = fmaxf(m.x, t.x); m.y = fmaxf(m.y, t.y);
        t = R1[tid + 2*RWW];   m.x = fmaxf(m.x, t.x); m.y = fmaxf(m.y, t.y);
        t = R2[tid];           m.x = fmaxf(m.x, t.x); m.y = fmaxf(m.y, t.y);
        t = R2[tid + RWW];     m.x = fmaxf(m.x, t.x); m.y = fmaxf(m.y, t.y);
        t = R2[tid + 2*RWW];   m.x = fmaxf(m.x, t.x); m.y = fmaxf(m.y, t.y);
        float dx = fmaxf(a.x - m.x, 0.0f);
        float dy = fmaxf(a.y - m.y, 0.0f);
        float2* S = (float2*)pS;
        if (FIRST) {
            float2 o; o.x = dx; o.y = dy;
            S[gw] = o;
        } else {
            float2 s = sPre;
            s.x = s.x + fmaxf(dx - s.x * dx, 0.0f);
            s.y = s.y + fmaxf(dy - s.y * dy, 0.0f);
            S[gw] = s;
        }
    };

    // ===================== prologue (slot(j) = j mod 6) ====================
    loadAfn(Ab + (z0 - 2) * PLANE, z0 - 2 >= 0, 4);
    loadAfn(Ab + (z0 - 1) * PLANE, z0 - 1 >= 0, 5);
    loadAfn(Ab + (z0    ) * PLANE, true, 0);
    loadAfn(Ab + (z0 + 1) * PLANE, true, 1);
    loadAfn(Ab + (z0 + 2) * PLANE, true, 2);
    loadAfn(Ab + (z0 + 3) * PLANE, true, 3);
    __syncthreads();

    ldPrefetch(Ab + (z0 + 4) * PLANE, Ab + (z0 + 5) * PLANE, true, true);
    er(5, 4, 0, z0 - 1 >= 0, false, EbB);                 // rx(z0-1)
    capA  = er(0, 5, 1, true, true, EbB + (z0    ) * PLANE);  // rx(z0), A(z0)
    capB  = er(1, 0, 2, true, true, EbB + (z0 + 1) * PLANE);  // rx(z0+1)
    carry = er(2, 1, 3, true, true, EbB + (z0 + 2) * PLANE);  // rx(z0+2)
    __syncthreads();

    stsPrefetch(4, 5);                                    // planes z0+4, z0+5
    ldPrefetch(Ab + (z0 + 6) * PLANE, Ab + (z0 + 7) * PLANE, true, true);
    __syncthreads();

    // ===================== main loop: 23 bodies, 2 planes, 1 sync ==========
    const float* pA = Ab  + (z0 + 8) * PLANE;  // next ldPrefetch: w+6
    float* pE       = EbB + (z0 + 3) * PLANE;  // E stores w+1, w+2
    float* pS       = SbB + (z0    ) * PLANE;  // outputs w-2, w-1
    int w = z0 + 2;

    auto body = [&](int c1, int m1, int p1, int c2, int m2, int p2,
                    int L1, int L2,
                    int a0, int a1, int a2, int b0s, int b1s, int b2s)
    {
        // phase A
        stsPrefetch(L1, L2);                       // planes w+4, w+5
        ldPrefetch(pA, pA + PLANE,                 // planes w+6, w+7
                   (w + 6) < DD, (w + 7) < DD);
        float2 dn0 = er(c1, m1, p1, true,         true,         pE);
        float2 dn1 = er(c2, m2, p2, (w + 2) < DD, (w + 2) < z1, pE + PLANE);
        // phase B (slot-disjoint from phase A writes; no mid-body sync)
        float2 sp0 = PINF2, sp1 = PINF2;
        if (!FIRST) {
            sp0 = ((const float2*)pS)[gw];
            sp1 = ((const float2*)(pS + PLANE))[gw];
        }
        do_output(a0,  a1,  a2,  pS,         capA, sp0);
        do_output(b0s, b1s, b2s, pS + PLANE, capB, sp1);
        capA = carry; capB = dn0; carry = dn1;
        __syncthreads();
        pA += 2 * PLANE; pE += 2 * PLANE; pS += 2 * PLANE;
        w += 2;
    };

    // phase tables (w%6 == 2 / 4 / 0); rx slot == C slot
    #pragma unroll 1
    for (int m = 0; m < 7; m++) {
        body(3,2,4, 4,3,5, 0,1, 5,0,1, 0,1,2);
        body(5,4,0, 0,5,1, 2,3, 1,2,3, 2,3,4);
        body(1,0,2, 2,1,3, 4,5, 3,4,5, 4,5,0);
    }
    body(3,2,4, 4,3,5, 0,1, 5,0,1, 0,1,2);   // w = z0+44
    body(5,4,0, 0,5,1, 2,3, 1,2,3, 2,3,4);   // w = z0+46

    // epilogue: outputs z0+46 (slots 3,4,5) and z0+47 (slots 4,5,0)
    float2 es0 = PINF2, es1 = PINF2;
    if (!FIRST) {
        es0 = ((const float2*)pS)[gw];
        es1 = ((const float2*)(pS + PLANE))[gw];
    }
    do_output(3, 4, 5, pS,         capA, es0);
    do_output(4, 5, 0, pS + PLANE, capB, es1);
}

extern "C" void kernel_launch(void* const* d_in, const int* in_sizes, int n_in,
                              void* d_out, int out_size) {
    const float* img = (const float*)d_in[0];
    float* skel = (float*)d_out;

    float *b0 = nullptr, *b1 = nullptr;
    cudaGetSymbolAddress((void**)&b0, g_buf0);
    cudaGetSymbolAddress((void**)&b1, g_buf1);

    cudaFuncSetAttribute((const void*)fused_step<1>,
                         cudaFuncAttributeMaxDynamicSharedMemorySize, SM_BYTES);
    cudaFuncSetAttribute((const void*)fused_step<0>,
                         cudaFuncAttributeMaxDynamicSharedMemorySize, SM_BYTES);

    dim3 grid(WW / 32, HH / 32, NCH * B);   // 6 x 6 x 8 = 288 blocks
    dim3 blk(NTHR, 1, 1);                   // 512 threads

    fused_step<1><<<grid, blk, SM_BYTES>>>(img, b0, skel);
    const float* src = b0;
    for (int kk = 1; kk <= 40; kk++) {
        float* dst = (kk & 1) ? b1 : b0;
        fused_step<0><<<grid, blk, SM_BYTES>>>(src, dst, skel);
        src = dst;
    }
}

// round 17
// speedup vs baseline: 1.6183x; 1.6183x over previous
#include <cuda_runtime.h>
#include <math_constants.h>

// Shapes: img (B=2, C=1, D=192, H=192, W=192) float32.
static constexpr int B   = 2;
static constexpr int DD  = 192;
static constexpr int HH  = 192;
static constexpr int WW  = 192;
static constexpr int PLANE = HH * WW;        // 36864
static constexpr int VOL   = DD * PLANE;     // 7077888
static constexpr int NTOT  = B * VOL;        // 14155776
static constexpr int WWW   = WW / 2;         // 96 gmem float2 words/row

static constexpr int NTHR = 512;
static constexpr int ZCHUNK = 48;            // z0 % 12 == 0
static constexpr int NCH    = DD / ZCHUNK;   // 4

// float2-word smem geometry
static constexpr int AWW = 18;               // A: 36 rows x 18 words (halo 2)
static constexpr int APW = 36 * AWW;         // 648
static constexpr int EWW = 18;               // e: 34 rows x 18 words (col c -> float idx c+1)
static constexpr int EPW = 34 * EWW;         // 612
static constexpr int RWW = 16;               // rz: 34 rows x 16 words
static constexpr int RPW = 34 * RWW;         // 544

static constexpr int SM_BYTES = (6 * APW + 4 * RPW + 2 * EPW) * 8;  // 58304

// Ping-pong erosion buffers (scratch: __device__ globals, no allocation).
__device__ float g_buf0[NTOT];
__device__ float g_buf1[NTOT];

__device__ __forceinline__ float2 fmax2(float2 a, float2 b) {
    float2 r; r.x = fmaxf(a.x, b.x); r.y = fmaxf(a.y, b.y); return r;
}

// One fused soft-skeletonize step:
//   Eout = soft_erode(A)                 (7-pt cross min, +inf pad)
//   d    = dilate3x3x3(Eout)             (-inf pad)
//   delta = relu(A - d)
//   skel  = FIRST ? delta : skel + relu(delta - skel*delta)
// float2 datapath; z-fold of the dilate done in registers (rz ring holds
// max over 3 z of the x-rowmax), so do_output needs only 3 LDS.
template <int FIRST>
__global__ __launch_bounds__(NTHR, 2)
void fused_step(const float* __restrict__ A,
                float* __restrict__ Eout,
                float* __restrict__ skel)
{
    extern __shared__ float2 sm2[];
    float2* As2 = sm2;                        // 6 A planes, slot = j%6
    float2* rz2 = sm2 + 6 * APW;              // 4 rz planes, slot = j%4
    float2* eb2 = sm2 + 6 * APW + 4 * RPW;    // 2 scratch erode planes

    const int tid = threadIdx.x;
    const int x0  = blockIdx.x * 32;
    const int y0  = blockIdx.y * 32;
    const int bz  = blockIdx.z;
    const int bb  = bz >> 2;                  // NCH == 4
    const int z0  = (bz & 3) * ZCHUNK;        // z0 % 12 == 0
    const int z1  = z0 + ZCHUNK;

    const float* __restrict__ Ab = A    + bb * VOL;
    float* __restrict__ EbB      = Eout + bb * VOL;
    float* __restrict__ SbB      = skel + bb * VOL;

    const float NINF = -CUDART_INF_F;
    const float2 PINF2 = make_float2(CUDART_INF_F, CUDART_INF_F);
    const float2 NINF2 = make_float2(NINF, NINF);

    // ================= z-invariant per-thread precomputation ==============
    const int r = tid >> 4;                   // 0..31
    const int k = tid & 15;

    const int  bA   = (r + 1) * AWW + k;      // A word base (e row r)
    const int  eStM = r * EWW + k + 1;        // eb store word (main)
    const bool valE = ((unsigned)(y0 + r - 1) < (unsigned)HH);
    const bool stM  = (r >= 1);               // e rows 1..31 stored
    const int  gEM  = (y0 + r - 1) * WWW + (x0 >> 1) + k;

    const bool act2e = tid < 32;              // second e rows 32,33 (warp 0)
    const bool stM2  = tid < 16;              // row 32 stored
    const bool valE2 = (tid < 16) || (y0 < 160);

    // e edge scalars (tid in [64,132)): cols 0 and 33, rows 0..33
    const bool actEd = (tid >= 64) && (tid < 132);
    int aE = 0, eStE = 0; bool valEd = false;
    {
        int j   = tid - 64;
        int col = (j & 1) ? 33 : 0;
        int row = j >> 1;
        aE   = (row + 1) * 36 + (col + 1);    // A float idx
        eStE = row * 36 + (col + 1);          // e float idx
        int gx = x0 + col - 1;
        int gy = y0 + row - 1;
        valEd = actEd && ((unsigned)gx < (unsigned)WW) &&
                         ((unsigned)gy < (unsigned)HH);
    }

    const int rbM = r * EWW + k;              // rx read base in eb
    const int gw  = (y0 + r) * WWW + (x0 >> 1) + k;   // out word

    // loadA: 648 words = 512 + 136
    const bool actL1 = tid < (APW - NTHR);
    int la0g, la1g; bool la0v, la1v;
    {
        int row0 = tid / AWW, c0 = tid - row0 * AWW;
        int gy = y0 + row0 - 2, gx = x0 + 2 * c0 - 2;
        la0v = ((unsigned)gy < (unsigned)HH) && ((unsigned)gx < (unsigned)WW);
        la0g = la0v ? gy * WWW + (gx >> 1) : 0;
        int wi = tid + NTHR;
        int row1 = wi / AWW, c1 = wi - row1 * AWW;
        gy = y0 + row1 - 2; gx = x0 + 2 * c1 - 2;
        la1v = actL1 && ((unsigned)gy < (unsigned)HH) && ((unsigned)gx < (unsigned)WW);
        la1g = la1v ? gy * WWW + (gx >> 1) : 0;
    }

    float2 capA, capB, carry;                 // A-center carries
    float2 rxPrev, pairPrev;                  // z-fold carries (main row)
    float2 rxPrev2, pairPrev2;                // z-fold carries (warp0 rows)
    float2 pf0a, pf0b, pf1a, pf1b;            // prefetched A planes

    // ========================= helpers ====================================

    auto loadAfn = [&](const float* src, bool zv, int slot) {
        float2* s = As2 + slot * APW;
        const float2* g = (const float2*)src;
        float2 v0 = (zv && la0v) ? __ldg(g + la0g) : PINF2;
        s[tid] = v0;
        if (actL1) {
            float2 v1 = (zv && la1v) ? __ldg(g + la1g) : PINF2;
            s[tid + NTHR] = v1;
        }
    };

    auto ldPrefetch = [&](const float* srcA, const float* srcB,
                          bool zvA, bool zvB) {
        const float2* g0 = (const float2*)srcA;
        const float2* g1 = (const float2*)srcB;
        pf0a = (zvA && la0v) ? __ldg(g0 + la0g) : PINF2;
        pf1a = (zvB && la0v) ? __ldg(g1 + la0g) : PINF2;
        if (actL1) {
            pf0b = (zvA && la1v) ? __ldg(g0 + la1g) : PINF2;
            pf1b = (zvB && la1v) ? __ldg(g1 + la1g) : PINF2;
        }
    };

    auto stsPrefetch = [&](int slotA, int slotB) {
        As2[slotA * APW + tid] = pf0a;
        As2[slotB * APW + tid] = pf1a;
        if (actL1) {
            As2[slotA * APW + tid + NTHR] = pf0b;
            As2[slotB * APW + tid + NTHR] = pf1b;
        }
    };

    // Erode plane into eb[ep]; store E to gmem from regs; return dn word
    // (A-center of the out row for this plane).
    auto compute_e = [&](int ep, int sC, int sM, int sP, bool jv,
                         bool st, float* pE) -> float2 {
        float2* E = eb2 + ep * EPW;
        const float2* C = As2 + sC * APW;
        const float2* M = As2 + sM * APW;
        const float2* P = As2 + sP * APW;
        float2 dn;
        {   // main pair: e cols 2k+1, 2k+2 at e-row r
            float2 w0 = C[bA], w1 = C[bA + 1], w2 = C[bA + 2];
            float2 up = C[bA + 1 - AWW];
            dn = C[bA + 1 + AWW];
            float2 zm = M[bA + 1], zp = P[bA + 1];
            float e0 = fminf(fminf(w1.x, fminf(up.x, dn.x)), fminf(zm.x, zp.x));
            e0 = fminf(e0, fminf(w0.y, w1.y));
            float e1 = fminf(fminf(w1.y, fminf(up.y, dn.y)), fminf(zm.y, zp.y));
            e1 = fminf(e1, fminf(w1.x, w2.x));
            bool v = jv && valE;
            float2 o; o.x = v ? e0 : NINF; o.y = v ? e1 : NINF;
            E[eStM] = o;
            if (st && stM) ((float2*)pE)[gEM] = o;
        }
        if (act2e) {  // rows 32,33
            const int bA2 = bA + 32 * AWW;
            float2 w0 = C[bA2], w1 = C[bA2 + 1], w2 = C[bA2 + 2];
            float2 up = C[bA2 + 1 - AWW], dn2 = C[bA2 + 1 + AWW];
            float2 zm = M[bA2 + 1], zp = P[bA2 + 1];
            float e0 = fminf(fminf(w1.x, fminf(up.x, dn2.x)), fminf(zm.x, zp.x));
            e0 = fminf(e0, fminf(w0.y, w1.y));
            float e1 = fminf(fminf(w1.y, fminf(up.y, dn2.y)), fminf(zm.y, zp.y));
            e1 = fminf(e1, fminf(w1.x, w2.x));
            bool v = jv && valE2;
            float2 o; o.x = v ? e0 : NINF; o.y = v ? e1 : NINF;
            E[eStM + 32 * EWW] = o;
            if (st && stM2) ((float2*)pE)[gEM + 32 * WWW] = o;
        }
        if (actEd) {  // scalar edge cols 0 / 33
            const float* Cf = (const float*)C;
            float m = fminf(Cf[aE], fminf(Cf[aE - 1], Cf[aE + 1]));
            m = fminf(m, fminf(Cf[aE - 36], Cf[aE + 36]));
            m = fminf(m, fminf(((const float*)M)[aE], ((const float*)P)[aE]));
            ((float*)E)[eStE] = (jv && valEd) ? m : NINF;
        }
        return dn;
    };

    // x-rowmax of eb[ep]: main row into rOut, warp0 rows into rOut2.
    auto rxcalc = [&](int ep, float2& rOut, float2& rOut2) {
        const float2* E = eb2 + ep * EPW;
        {
            float2 w0 = E[rbM], w1 = E[rbM + 1], w2 = E[rbM + 2];
            float c = fmaxf(w1.x, w1.y);
            rOut.x = fmaxf(w0.y, c);
            rOut.y = fmaxf(c, w2.x);
        }
        if (act2e) {
            const int rb2 = rbM + 32 * EWW;
            float2 w0 = E[rb2], w1 = E[rb2 + 1], w2 = E[rb2 + 2];
            float c = fmaxf(w1.x, w1.y);
            rOut2.x = fmaxf(w0.y, c);
            rOut2.y = fmaxf(c, w2.x);
        }
    };

    auto rzStore = [&](int slot, float2 v, float2 v2) {
        rz2[slot * RPW + tid] = v;
        if (act2e) rz2[slot * RPW + NTHR + tid] = v2;
    };

    auto do_output = [&](int rzSlot, float* pS, float2 a, float2 sPre) {
        const float2* R = rz2 + rzSlot * RPW;
        float2 m = R[tid];
        m = fmax2(m, R[tid + RWW]);
        m = fmax2(m, R[tid + 2 * RWW]);
        float dx = fmaxf(a.x - m.x, 0.0f);
        float dy = fmaxf(a.y - m.y, 0.0f);
        float2* S = (float2*)pS;
        if (FIRST) {
            float2 o; o.x = dx; o.y = dy;
            S[gw] = o;
        } else {
            float2 s = sPre;
            s.x = s.x + fmaxf(dx - s.x * dx, 0.0f);
            s.y = s.y + fmaxf(dy - s.y * dy, 0.0f);
            S[gw] = s;
        }
    };

    // ===================== prologue (A slot = j%6, rz slot = j%4) ==========
    loadAfn(Ab + (z0 - 2) * PLANE, z0 - 2 >= 0, 4);
    loadAfn(Ab + (z0 - 1) * PLANE, z0 - 1 >= 0, 5);
    loadAfn(Ab + (z0    ) * PLANE, true, 0);
    loadAfn(Ab + (z0 + 1) * PLANE, true, 1);
    loadAfn(Ab + (z0 + 2) * PLANE, true, 2);
    loadAfn(Ab + (z0 + 3) * PLANE, true, 3);
    __syncthreads();

    ldPrefetch(Ab + (z0 + 4) * PLANE, Ab + (z0 + 5) * PLANE, true, true);
    compute_e(0, 5, 4, 0, z0 - 1 >= 0, false, EbB);             // e(z0-1)
    capA = compute_e(1, 0, 5, 1, true, true, EbB + z0 * PLANE); // e(z0)
    __syncthreads();

    float2 rxm1, rxm1b = NINF2, rx0, rx0b = NINF2;
    rxcalc(0, rxm1, rxm1b);
    rxcalc(1, rx0, rx0b);
    __syncthreads();                          // before eb reuse

    capB  = compute_e(0, 1, 0, 2, true, true, EbB + (z0 + 1) * PLANE);
    carry = compute_e(1, 2, 1, 3, true, true, EbB + (z0 + 2) * PLANE);
    stsPrefetch(4, 5);                        // planes z0+4, z0+5
    ldPrefetch(Ab + (z0 + 6) * PLANE, Ab + (z0 + 7) * PLANE, true, true);
    __syncthreads();

    {
        float2 rx1, rx1b = NINF2, rx2v, rx2b = NINF2;
        rxcalc(0, rx1, rx1b);
        rxcalc(1, rx2v, rx2b);
        rzStore(0, fmax2(fmax2(rxm1, rx0), rx1),
                   fmax2(fmax2(rxm1b, rx0b), rx1b));       // rz(z0)
        rzStore(1, fmax2(fmax2(rx0, rx1), rx2v),
                   fmax2(fmax2(rx0b, rx1b), rx2b));        // rz(z0+1)
        pairPrev  = fmax2(rx1, rx2v);  rxPrev  = rx2v;
        pairPrev2 = fmax2(rx1b, rx2b); rxPrev2 = rx2b;
    }
    __syncthreads();

    // ===================== main loop: 23 bodies, 2 planes each =============
    const float* pA = Ab  + (z0 + 8) * PLANE;  // ldPrefetch planes w+6, w+7
    float* pE       = EbB + (z0 + 3) * PLANE;  // E stores w+1, w+2
    float* pS       = SbB + (z0    ) * PLANE;  // outputs w-2, w-1
    int w = z0 + 2;

    auto body = [&](int c1, int m1, int p1, int c2, int m2, int p2,
                    int L1, int L2, int W0, int W1, int R0, int R1)
    {
        // phase A
        stsPrefetch(L1, L2);                       // planes w+4, w+5
        ldPrefetch(pA, pA + PLANE,                 // planes w+6, w+7
                   (w + 6) < DD, (w + 7) < DD);
        float2 dn0 = compute_e(0, c1, m1, p1, true,         true,         pE);
        float2 dn1 = compute_e(1, c2, m2, p2, (w + 2) < DD, (w + 2) < z1, pE + PLANE);
        __syncthreads();
        // phase B
        float2 sp0 = PINF2, sp1 = PINF2;
        if (!FIRST) {
            sp0 = ((const float2*)pS)[gw];
            sp1 = ((const float2*)(pS + PLANE))[gw];
        }
        float2 rxA, rxA2 = NINF2, rxB, rxB2 = NINF2;
        rxcalc(0, rxA, rxA2);                      // rx(w+1)
        rzStore(W0, fmax2(pairPrev, rxA), fmax2(pairPrev2, rxA2));  // rz(w)
        float2 pairA  = fmax2(rxPrev,  rxA);
        float2 pairA2 = fmax2(rxPrev2, rxA2);
        rxcalc(1, rxB, rxB2);                      // rx(w+2)
        rzStore(W1, fmax2(pairA, rxB), fmax2(pairA2, rxB2));        // rz(w+1)
        pairPrev  = fmax2(rxA, rxB);   rxPrev  = rxB;
        pairPrev2 = fmax2(rxA2, rxB2); rxPrev2 = rxB2;
        do_output(R0, pS,         capA, sp0);      // out(w-2)
        do_output(R1, pS + PLANE, capB, sp1);      // out(w-1)
        capA = carry; capB = dn0; carry = dn1;
        __syncthreads();
        pA += 2 * PLANE; pE += 2 * PLANE; pS += 2 * PLANE;
        w += 2;
    };

    // phase tables keyed on w%12 (A slots = w%6 cycle, rz slots = w%4 cycle)
    #pragma unroll 1
    for (int m = 0; m < 3; m++) {
        body(3,2,4, 4,3,5, 0,1, 2,3, 0,1);   // w%12 == 2
        body(5,4,0, 0,5,1, 2,3, 0,1, 2,3);   // w%12 == 4
        body(1,0,2, 2,1,3, 4,5, 2,3, 0,1);   // w%12 == 6
        body(3,2,4, 4,3,5, 0,1, 0,1, 2,3);   // w%12 == 8
        body(5,4,0, 0,5,1, 2,3, 2,3, 0,1);   // w%12 == 10
        body(1,0,2, 2,1,3, 4,5, 0,1, 2,3);   // w%12 == 0
    }
    body(3,2,4, 4,3,5, 0,1, 2,3, 0,1);       // w = z0+38
    body(5,4,0, 0,5,1, 2,3, 0,1, 2,3);       // w = z0+40
    body(1,0,2, 2,1,3, 4,5, 2,3, 0,1);       // w = z0+42
    body(3,2,4, 4,3,5, 0,1, 0,1, 2,3);       // w = z0+44
    body(5,4,0, 0,5,1, 2,3, 2,3, 0,1);       // w = z0+46

    // epilogue: outputs z0+46 (rz slot 2) and z0+47 (rz slot 3)
    float2 es0 = PINF2, es1 = PINF2;
    if (!FIRST) {
        es0 = ((const float2*)pS)[gw];
        es1 = ((const float2*)(pS + PLANE))[gw];
    }
    do_output(2, pS,         capA, es0);
    do_output(3, pS + PLANE, capB, es1);
}

extern "C" void kernel_launch(void* const* d_in, const int* in_sizes, int n_in,
                              void* d_out, int out_size) {
    const float* img = (const float*)d_in[0];
    float* skel = (float*)d_out;

    float *b0 = nullptr, *b1 = nullptr;
    cudaGetSymbolAddress((void**)&b0, g_buf0);
    cudaGetSymbolAddress((void**)&b1, g_buf1);

    cudaFuncSetAttribute((const void*)fused_step<1>,
                         cudaFuncAttributeMaxDynamicSharedMemorySize, SM_BYTES);
    cudaFuncSetAttribute((const void*)fused_step<0>,
                         cudaFuncAttributeMaxDynamicSharedMemorySize, SM_BYTES);

    dim3 grid(WW / 32, HH / 32, NCH * B);   // 6 x 6 x 8 = 288 blocks
    dim3 blk(NTHR, 1, 1);                   // 512 threads

    fused_step<1><<<grid, blk, SM_BYTES>>>(img, b0, skel);
    const float* src = b0;
    for (int kk = 1; kk <= 40; kk++) {
        float* dst = (kk & 1) ? b1 : b0;
        fused_step<0><<<grid, blk, SM_BYTES>>>(src, dst, skel);
        src = dst;
    }
}